// round 5
// baseline (speedup 1.0000x reference)
#include <cuda_runtime.h>
#include <cuda_bf16.h>
#include <cstdint>

// Problem constants
#define M_TOTAL 8192      // 4 * 2048
#define N_TOTAL 4096      // OUT_FEATURES
#define K_TOTAL 4096      // IN_FEATURES
#define BLOCKSIZE 64

// FP4 codebook (static-initialized constant memory; no runtime copy needed)
__constant__ float c_codebook[16] = {
    0.0f,  0.0052f,  0.6667f,  1.0f,  0.3333f,  0.5f,  0.1667f,  0.25f,
    0.0f, -0.0052f, -0.6667f, -1.0f, -0.3333f, -0.5f, -0.1667f, -0.25f
};

// Dequantized weight scratch (64 MB). Device global: allowed (no alloc).
__device__ float g_W[(size_t)N_TOTAL * K_TOTAL];

__device__ __forceinline__ float to_tf32(float x) {
    uint32_t u;
    asm("cvt.rna.tf32.f32 %0, %1;" : "=r"(u) : "f"(x));
    return __uint_as_float(u);
}

// ---------------------------------------------------------------------------
// Dequant: each thread unpacks one packed byte (stored as int32) -> 2 weights.
// Element e=2j (high nibble) and e=2j+1 (low nibble); both in scale block j>>5.
// Weights are pre-rounded to tf32 so the GEMM consumes them directly.
// ---------------------------------------------------------------------------
__global__ void dequant_kernel(const int* __restrict__ wp,
                               const float* __restrict__ scale,
                               int n_packed) {
    int j = blockIdx.x * blockDim.x + threadIdx.x;
    if (j >= n_packed) return;
    int b = wp[j];
    float s = scale[j >> 5];
    float hi = to_tf32(c_codebook[(b >> 4) & 15] * s);
    float lo = to_tf32(c_codebook[b & 15] * s);
    reinterpret_cast<float2*>(g_W)[j] = make_float2(hi, lo);
}

// ---------------------------------------------------------------------------
// GEMM: C[M,N] = A[M,K] * W[N,K]^T + bias
// Block tile 128x128x16, 256 threads = 8 warps (2 m-warps x 4 n-warps),
// warp tile 64x32 via m16n8k8 tf32 mma (4 m-frags x 4 n-frags).
// Smem tiles padded to stride 20 floats -> conflict-free fragment loads.
// Register double-buffered global->smem pipeline.
// ---------------------------------------------------------------------------
#define BM 128
#define BN 128
#define BK 16
#define SSTRIDE 20   // BK + 4 padding

__device__ __forceinline__ void mma_tf32(float c[4], const uint32_t a[4], const uint32_t b[2]) {
    asm volatile(
        "mma.sync.aligned.m16n8k8.row.col.f32.tf32.tf32.f32 "
        "{%0,%1,%2,%3}, {%4,%5,%6,%7}, {%8,%9}, {%0,%1,%2,%3};\n"
        : "+f"(c[0]), "+f"(c[1]), "+f"(c[2]), "+f"(c[3])
        : "r"(a[0]), "r"(a[1]), "r"(a[2]), "r"(a[3]),
          "r"(b[0]), "r"(b[1]));
}

__global__ void __launch_bounds__(256)
gemm_tf32_kernel(const float* __restrict__ A,    // [M, K] row-major
                 const float* __restrict__ bias, // [N]
                 float* __restrict__ C)          // [M, N] row-major
{
    __shared__ float As[2][BM * SSTRIDE];
    __shared__ float Bs[2][BN * SSTRIDE];

    const int tid     = threadIdx.x;
    const int lane    = tid & 31;
    const int warp_id = tid >> 5;
    const int warp_m  = warp_id & 1;   // 0..1
    const int warp_n  = warp_id >> 1;  // 0..3
    const int gid     = lane >> 2;     // 0..7
    const int tig     = lane & 3;      // 0..3

    const int block_n = blockIdx.x;
    const int block_m = blockIdx.y;

    const float* Ablk = A   + (size_t)block_m * BM * K_TOTAL;
    const float* Bblk = g_W + (size_t)block_n * BN * K_TOTAL;

    // Global-load addressing: 256 threads, each loads 2 float4 per tile.
    const int r0 = tid >> 2;        // 0..63
    const int c0 = (tid & 3) << 2;  // 0,4,8,12

    float acc[4][4][4];
#pragma unroll
    for (int mi = 0; mi < 4; mi++)
#pragma unroll
        for (int ni = 0; ni < 4; ni++)
#pragma unroll
            for (int i = 0; i < 4; i++) acc[mi][ni][i] = 0.0f;

    const int kt_count = K_TOTAL / BK;  // 256
    float4 ra0, ra1, rb0, rb1;

    // Prologue: load tile 0
    {
        const float* ap = Ablk + r0 * K_TOTAL + c0;
        ra0 = *reinterpret_cast<const float4*>(ap);
        ra1 = *reinterpret_cast<const float4*>(ap + 64 * K_TOTAL);
        const float* bp = Bblk + r0 * K_TOTAL + c0;
        rb0 = *reinterpret_cast<const float4*>(bp);
        rb1 = *reinterpret_cast<const float4*>(bp + 64 * K_TOTAL);
        float* sa = &As[0][r0 * SSTRIDE + c0];
        sa[0] = to_tf32(ra0.x); sa[1] = to_tf32(ra0.y); sa[2] = to_tf32(ra0.z); sa[3] = to_tf32(ra0.w);
        float* sa2 = sa + 64 * SSTRIDE;
        sa2[0] = to_tf32(ra1.x); sa2[1] = to_tf32(ra1.y); sa2[2] = to_tf32(ra1.z); sa2[3] = to_tf32(ra1.w);
        float* sb = &Bs[0][r0 * SSTRIDE + c0];
        sb[0] = rb0.x; sb[1] = rb0.y; sb[2] = rb0.z; sb[3] = rb0.w;
        float* sb2 = sb + 64 * SSTRIDE;
        sb2[0] = rb1.x; sb2[1] = rb1.y; sb2[2] = rb1.z; sb2[3] = rb1.w;
    }
    __syncthreads();

    const int arow = warp_m * 64 + gid;
    const int brow = warp_n * 32 + gid;

    for (int kt = 0; kt < kt_count; ++kt) {
        const int cur = kt & 1;
        const int nxt = cur ^ 1;

        // Issue next tile's global loads (overlap with compute)
        if (kt + 1 < kt_count) {
            const float* ap = Ablk + r0 * K_TOTAL + (kt + 1) * BK + c0;
            ra0 = *reinterpret_cast<const float4*>(ap);
            ra1 = *reinterpret_cast<const float4*>(ap + 64 * K_TOTAL);
            const float* bp = Bblk + r0 * K_TOTAL + (kt + 1) * BK + c0;
            rb0 = *reinterpret_cast<const float4*>(bp);
            rb1 = *reinterpret_cast<const float4*>(bp + 64 * K_TOTAL);
        }

        // Compute on current smem buffers
        const float* Asb = As[cur];
        const float* Bsb = Bs[cur];
#pragma unroll
        for (int kk = 0; kk < 2; ++kk) {
            const int k0 = kk * 8;
            uint32_t af[4][4];
            uint32_t bf[4][2];
#pragma unroll
            for (int mi = 0; mi < 4; mi++) {
                const float* p  = Asb + (arow + mi * 16) * SSTRIDE + k0 + tig;
                const float* p8 = p + 8 * SSTRIDE;
                af[mi][0] = __float_as_uint(p[0]);
                af[mi][1] = __float_as_uint(p8[0]);
                af[mi][2] = __float_as_uint(p[4]);
                af[mi][3] = __float_as_uint(p8[4]);
            }
#pragma unroll
            for (int ni = 0; ni < 4; ni++) {
                const float* p = Bsb + (brow + ni * 8) * SSTRIDE + k0 + tig;
                bf[ni][0] = __float_as_uint(p[0]);
                bf[ni][1] = __float_as_uint(p[4]);
            }
#pragma unroll
            for (int mi = 0; mi < 4; mi++)
#pragma unroll
                for (int ni = 0; ni < 4; ni++)
                    mma_tf32(acc[mi][ni], af[mi], bf[ni]);
        }

        // Stage next tile into the other smem buffer
        if (kt + 1 < kt_count) {
            float* sa = &As[nxt][r0 * SSTRIDE + c0];
            sa[0] = to_tf32(ra0.x); sa[1] = to_tf32(ra0.y); sa[2] = to_tf32(ra0.z); sa[3] = to_tf32(ra0.w);
            float* sa2 = sa + 64 * SSTRIDE;
            sa2[0] = to_tf32(ra1.x); sa2[1] = to_tf32(ra1.y); sa2[2] = to_tf32(ra1.z); sa2[3] = to_tf32(ra1.w);
            float* sb = &Bs[nxt][r0 * SSTRIDE + c0];
            sb[0] = rb0.x; sb[1] = rb0.y; sb[2] = rb0.z; sb[3] = rb0.w;
            float* sb2 = sb + 64 * SSTRIDE;
            sb2[0] = rb1.x; sb2[1] = rb1.y; sb2[2] = rb1.z; sb2[3] = rb1.w;
        }
        __syncthreads();
    }

    // Epilogue: C = acc + bias (float2 stores, c is even -> 8B aligned)
    const int m_base = block_m * BM + warp_m * 64;
    const int n_base = block_n * BN + warp_n * 32;
#pragma unroll
    for (int mi = 0; mi < 4; mi++) {
#pragma unroll
        for (int ni = 0; ni < 4; ni++) {
            const int r = m_base + mi * 16 + gid;
            const int c = n_base + ni * 8 + tig * 2;
            const float b0 = bias[c];
            const float b1 = bias[c + 1];
            float2 v0 = make_float2(acc[mi][ni][0] + b0, acc[mi][ni][1] + b1);
            float2 v1 = make_float2(acc[mi][ni][2] + b0, acc[mi][ni][3] + b1);
            *reinterpret_cast<float2*>(C + (size_t)r * N_TOTAL + c)       = v0;
            *reinterpret_cast<float2*>(C + (size_t)(r + 8) * N_TOTAL + c) = v1;
        }
    }
}

extern "C" void kernel_launch(void* const* d_in, const int* in_sizes, int n_in,
                              void* d_out, int out_size) {
    const float* x      = (const float*)d_in[0];   // [4,2048,4096]
    const int*   wp     = (const int*)d_in[1];     // [8388608] packed bytes
    const float* scale  = (const float*)d_in[2];   // [262144]
    const float* bias   = (const float*)d_in[3];   // [4096]
    float*       out    = (float*)d_out;           // [4,2048,4096]

    const int n_packed = in_sizes[1];  // 8388608
    dequant_kernel<<<(n_packed + 255) / 256, 256>>>(wp, scale, n_packed);

    dim3 grid(N_TOTAL / BN, M_TOTAL / BM);  // (32, 64)
    gemm_tf32_kernel<<<grid, 256>>>(x, bias, out);
}

// round 7
// speedup vs baseline: 1.3868x; 1.3868x over previous
#include <cuda_runtime.h>
#include <cstdint>

// ---------------------------------------------------------------------------
// Problem constants
// ---------------------------------------------------------------------------
#define M_TOTAL 8192      // 4 * 2048
#define N_TOTAL 4096      // OUT_FEATURES
#define K_TOTAL 4096      // IN_FEATURES

__constant__ float c_codebook[16] = {
    0.0f,  0.0052f,  0.6667f,  1.0f,  0.3333f,  0.5f,  0.1667f,  0.25f,
    0.0f, -0.0052f, -0.6667f, -1.0f, -0.3333f, -0.5f, -0.1667f, -0.25f
};

// Scratch buffers (device globals: no runtime allocation).
// Both hold K-permuted data: within each 16-float K-group, element with
// original index k is stored at position q(k) = 4*(k&3) + (k>>2).
// This makes each mma thread's fragment k-values {tig, tig+4, tig+8, tig+12}
// contiguous -> one LDS.128 per fragment pair.
__device__ __align__(256) float g_W[(size_t)N_TOTAL * K_TOTAL];   // 64 MB
__device__ __align__(256) float g_X[(size_t)M_TOTAL * K_TOTAL];   // 128 MB

__device__ __forceinline__ float to_tf32(float x) {
    uint32_t u;
    asm("cvt.rna.tf32.f32 %0, %1;" : "=r"(u) : "f"(x));
    return __uint_as_float(u);
}

// ---------------------------------------------------------------------------
// Dequant + permute: each thread produces one 16-element K-group of W.
// 16 elements = 8 packed bytes = 8 int32 inputs (one byte per int).
// ---------------------------------------------------------------------------
__global__ void dequant_permute_kernel(const int* __restrict__ wp,
                                       const float* __restrict__ scale) {
    const int g = blockIdx.x * blockDim.x + threadIdx.x;
    if (g >= (N_TOTAL * K_TOTAL) / 16) return;
    const int4 p0 = reinterpret_cast<const int4*>(wp)[2 * g];
    const int4 p1 = reinterpret_cast<const int4*>(wp)[2 * g + 1];
    const float s = scale[g >> 2];   // 16 elements per group, 64 per block

    int b[8] = {p0.x, p0.y, p0.z, p0.w, p1.x, p1.y, p1.z, p1.w};
    float v[16];
#pragma unroll
    for (int j = 0; j < 8; j++) {
        v[2 * j]     = to_tf32(c_codebook[(b[j] >> 4) & 15] * s);
        v[2 * j + 1] = to_tf32(c_codebook[b[j] & 15] * s);
    }
    // out position p holds original k = (p&3)*4 + (p>>2)
    float4* o = reinterpret_cast<float4*>(g_W + (size_t)g * 16);
#pragma unroll
    for (int q = 0; q < 4; q++)
        o[q] = make_float4(v[0 * 4 + q], v[1 * 4 + q], v[2 * 4 + q], v[3 * 4 + q]);
}

// ---------------------------------------------------------------------------
// Permute x into g_X (4x4 transpose within each 16-float K-group).
// A values stay full fp32 (tensor core truncates to tf32 internally).
// ---------------------------------------------------------------------------
__global__ void permute_x_kernel(const float* __restrict__ x) {
    const int g = blockIdx.x * blockDim.x + threadIdx.x;
    if (g >= (M_TOTAL * K_TOTAL) / 16) return;
    const float4* in = reinterpret_cast<const float4*>(x + (size_t)g * 16);
    float4 i0 = in[0], i1 = in[1], i2 = in[2], i3 = in[3];
    float4* o = reinterpret_cast<float4*>(g_X + (size_t)g * 16);
    o[0] = make_float4(i0.x, i1.x, i2.x, i3.x);
    o[1] = make_float4(i0.y, i1.y, i2.y, i3.y);
    o[2] = make_float4(i0.z, i1.z, i2.z, i3.z);
    o[3] = make_float4(i0.w, i1.w, i2.w, i3.w);
}

// ---------------------------------------------------------------------------
// GEMM: C[M,N] = X[M,K] * W[N,K]^T + bias
// Block 128x128xBK16, 256 threads = 8 warps (2m x 4n), warp tile 64x32.
// 5-stage cp.async pipeline, 16KB/stage, fragments via LDS.128.
// ---------------------------------------------------------------------------
#define BM 128
#define BN 128
#define BK 16
#define STAGES 5
#define STAGE_FLOATS (2 * BM * BK)          // A 2048 + B 2048 floats = 16 KB
#define B_FLOAT_OFF (BM * BK)               // 2048
#define NUM_KTILES (K_TOTAL / BK)           // 256

__device__ __forceinline__ uint32_t smem_u32(const void* p) {
    uint32_t a;
    asm("{ .reg .u64 t; cvta.to.shared.u64 t, %1; cvt.u32.u64 %0, t; }" : "=r"(a) : "l"(p));
    return a;
}
__device__ __forceinline__ void cp16(uint32_t dst, const float* src) {
    asm volatile("cp.async.cg.shared.global [%0], [%1], 16;" :: "r"(dst), "l"(src));
}
__device__ __forceinline__ void cp_commit() {
    asm volatile("cp.async.commit_group;");
}
template <int N>
__device__ __forceinline__ void cp_wait() {
    asm volatile("cp.async.wait_group %0;" :: "n"(N));
}

__device__ __forceinline__ void mma_tf32(float c[4], uint32_t a0, uint32_t a1,
                                         uint32_t a2, uint32_t a3,
                                         uint32_t b0, uint32_t b1) {
    asm volatile(
        "mma.sync.aligned.m16n8k8.row.col.f32.tf32.tf32.f32 "
        "{%0,%1,%2,%3}, {%4,%5,%6,%7}, {%8,%9}, {%0,%1,%2,%3};\n"
        : "+f"(c[0]), "+f"(c[1]), "+f"(c[2]), "+f"(c[3])
        : "r"(a0), "r"(a1), "r"(a2), "r"(a3), "r"(b0), "r"(b1));
}

__global__ void __launch_bounds__(256, 2)
gemm_tf32_kernel(const float* __restrict__ bias, float* __restrict__ C)
{
    extern __shared__ __align__(16) float smem[];   // STAGES * STAGE_FLOATS
    __shared__ float s_bias[BN];

    const int tid  = threadIdx.x;
    const int lane = tid & 31;
    const int wid  = tid >> 5;
    const int warp_m = wid & 1;
    const int warp_n = wid >> 1;
    const int gid = lane >> 2;
    const int tig = lane & 3;

    // Block swizzle: chunks of 8 m-tiles x 32 n-tiles (~256 CTAs ~ one wave)
    const int bid   = blockIdx.x;
    const int chunk = bid >> 8;
    const int rres  = bid & 255;
    const int bm    = chunk * 8 + (rres & 7);   // 0..63
    const int bn    = rres >> 3;                // 0..31

    const float* Ag = g_X + (size_t)bm * BM * K_TOTAL;
    const float* Bg = g_W + (size_t)bn * BN * K_TOTAL;

    if (tid < BN) s_bias[tid] = bias[bn * BN + tid];

    // Copy addressing: 512 16B-chunks per operand per tile; thread t does
    // rows r0 and r0+64, segment seg (16B each) for both A and B.
    const int r0  = tid >> 2;       // 0..63
    const int seg = tid & 3;        // 0..3
    const uint32_t smem_base = smem_u32(smem);
    const size_t g_off0 = (size_t)r0 * K_TOTAL + seg * 4;
    const size_t g_off1 = (size_t)(r0 + 64) * K_TOTAL + seg * 4;
    const uint32_t s_off = (uint32_t)(r0 * BK + seg * 4) * 4;   // bytes

    auto issue_tile = [&](int slot, int kt) {
        const uint32_t st = smem_base + (uint32_t)slot * (STAGE_FLOATS * 4);
        const float* a = Ag + (size_t)kt * BK;
        const float* b = Bg + (size_t)kt * BK;
        cp16(st + s_off,                          a + g_off0);
        cp16(st + s_off + 64 * BK * 4,            a + g_off1);
        cp16(st + s_off + B_FLOAT_OFF * 4,        b + g_off0);
        cp16(st + s_off + (B_FLOAT_OFF + 64 * BK) * 4, b + g_off1);
    };

    float acc[4][4][4];
#pragma unroll
    for (int mi = 0; mi < 4; mi++)
#pragma unroll
        for (int ni = 0; ni < 4; ni++)
#pragma unroll
            for (int i = 0; i < 4; i++) acc[mi][ni][i] = 0.0f;

    // Prologue: fill STAGES-1 stages
#pragma unroll
    for (int s = 0; s < STAGES - 1; s++) { issue_tile(s, s); cp_commit(); }

    const int arow = warp_m * 64 + gid;
    const int brow = warp_n * 32 + gid;

    for (int kt = 0; kt < NUM_KTILES; kt++) {
        cp_wait<STAGES - 2>();
        __syncthreads();

        // Start next DMA early (writes slot read in iteration kt-1: safe past sync)
        if (kt + STAGES - 1 < NUM_KTILES) issue_tile((kt + STAGES - 1) % STAGES, kt + STAGES - 1);
        cp_commit();

        const int slot = kt % STAGES;
        const float* Asb = smem + slot * STAGE_FLOATS;
        const float* Bsb = Asb + B_FLOAT_OFF;

        // Fragments: one float4 per (row, tig) covers kk0 and kk1.
        // layout pos 4*tig..+3 = original k {tig, tig+4, tig+8, tig+12}
        float4 alo[4], ahi[4], bfr[4];
#pragma unroll
        for (int mi = 0; mi < 4; mi++) {
            alo[mi] = *reinterpret_cast<const float4*>(Asb + (arow + mi * 16) * BK + 4 * tig);
            ahi[mi] = *reinterpret_cast<const float4*>(Asb + (arow + mi * 16 + 8) * BK + 4 * tig);
        }
#pragma unroll
        for (int ni = 0; ni < 4; ni++)
            bfr[ni] = *reinterpret_cast<const float4*>(Bsb + (brow + ni * 8) * BK + 4 * tig);

        // kk = 0 (original k 0..7): components .x (k=tig) and .y (k=tig+4)
#pragma unroll
        for (int mi = 0; mi < 4; mi++)
#pragma unroll
            for (int ni = 0; ni < 4; ni++)
                mma_tf32(acc[mi][ni],
                         __float_as_uint(alo[mi].x), __float_as_uint(ahi[mi].x),
                         __float_as_uint(alo[mi].y), __float_as_uint(ahi[mi].y),
                         __float_as_uint(bfr[ni].x), __float_as_uint(bfr[ni].y));
        // kk = 1 (original k 8..15): components .z (k=tig+8) and .w (k=tig+12)
#pragma unroll
        for (int mi = 0; mi < 4; mi++)
#pragma unroll
            for (int ni = 0; ni < 4; ni++)
                mma_tf32(acc[mi][ni],
                         __float_as_uint(alo[mi].z), __float_as_uint(ahi[mi].z),
                         __float_as_uint(alo[mi].w), __float_as_uint(ahi[mi].w),
                         __float_as_uint(bfr[ni].z), __float_as_uint(bfr[ni].w));
    }

    // Epilogue: C = acc + bias
    const int m_base = bm * BM + warp_m * 64;
    const int n_base = bn * BN + warp_n * 32;
#pragma unroll
    for (int mi = 0; mi < 4; mi++) {
#pragma unroll
        for (int ni = 0; ni < 4; ni++) {
            const int r = m_base + mi * 16 + gid;
            const int c = n_base + ni * 8 + tig * 2;
            const float b0 = s_bias[c - bn * BN];
            const float b1 = s_bias[c - bn * BN + 1];
            float2 v0 = make_float2(acc[mi][ni][0] + b0, acc[mi][ni][1] + b1);
            float2 v1 = make_float2(acc[mi][ni][2] + b0, acc[mi][ni][3] + b1);
            *reinterpret_cast<float2*>(C + (size_t)r * N_TOTAL + c)       = v0;
            *reinterpret_cast<float2*>(C + (size_t)(r + 8) * N_TOTAL + c) = v1;
        }
    }
}

// ---------------------------------------------------------------------------
// Launch
// ---------------------------------------------------------------------------
extern "C" void kernel_launch(void* const* d_in, const int* in_sizes, int n_in,
                              void* d_out, int out_size) {
    const float* x     = (const float*)d_in[0];   // [4,2048,4096]
    const int*   wp    = (const int*)d_in[1];     // packed bytes as int32
    const float* scale = (const float*)d_in[2];
    const float* bias  = (const float*)d_in[3];
    float*       out   = (float*)d_out;

    const int w_groups = (N_TOTAL * K_TOTAL) / 16;   // 1048576
    const int x_groups = (M_TOTAL * K_TOTAL) / 16;   // 2097152
    dequant_permute_kernel<<<w_groups / 256, 256>>>(wp, scale);
    permute_x_kernel<<<x_groups / 256, 256>>>(x);

    static const int smem_bytes = STAGES * STAGE_FLOATS * 4;   // 80 KB
    cudaFuncSetAttribute(gemm_tf32_kernel,
                         cudaFuncAttributeMaxDynamicSharedMemorySize, smem_bytes);
    const int grid = (M_TOTAL / BM) * (N_TOTAL / BN);   // 2048
    gemm_tf32_kernel<<<grid, 256, smem_bytes>>>(bias, out);
}

// round 8
// speedup vs baseline: 2.6084x; 1.8809x over previous
#include <cuda_runtime.h>
#include <cuda_fp16.h>
#include <cstdint>

// ---------------------------------------------------------------------------
// Problem constants
// ---------------------------------------------------------------------------
#define M_TOTAL 8192      // 4 * 2048
#define N_TOTAL 4096      // OUT_FEATURES
#define K_TOTAL 4096      // IN_FEATURES

__constant__ float c_codebook[16] = {
    0.0f,  0.0052f,  0.6667f,  1.0f,  0.3333f,  0.5f,  0.1667f,  0.25f,
    0.0f, -0.0052f, -0.6667f, -1.0f, -0.3333f, -0.5f, -0.1667f, -0.25f
};

// fp16 operand buffers, K-permuted (device globals: no runtime alloc).
// Within each 32-half K-group, positions 8t..8t+7 (t=0..3) hold original
// k = {2t,2t+1, 2t+8,2t+9, 16+2t,16+2t+1, 24+2t,24+2t+1}: thread tig=t reads
// one LDS.128 covering BOTH m16n8k16 k-steps of the 32-wide tile.
__device__ __align__(256) __half g_W[(size_t)N_TOTAL * K_TOTAL];   // 32 MB
__device__ __align__(256) __half g_X[(size_t)M_TOTAL * K_TOTAL];   // 64 MB

__device__ __forceinline__ uint32_t h2u(float a, float b) {
    __half2 h = __floats2half2_rn(a, b);   // .x = a (lower address)
    return *reinterpret_cast<uint32_t*>(&h);
}

// ---------------------------------------------------------------------------
// Dequant + permute: one thread -> one 32-element K-group of W (16 wp ints).
// Group g spans elements 32g..32g+31; scale block = g>>1 (BLOCKSIZE 64).
// ---------------------------------------------------------------------------
__global__ void dequant_permute_kernel(const int* __restrict__ wp,
                                       const float* __restrict__ scale) {
    const int g = blockIdx.x * blockDim.x + threadIdx.x;
    if (g >= (N_TOTAL * K_TOTAL) / 32) return;
    const int4* wp4 = reinterpret_cast<const int4*>(wp) + 4 * (size_t)g;
    int4 p0 = wp4[0], p1 = wp4[1], p2 = wp4[2], p3 = wp4[3];
    int b[16] = {p0.x, p0.y, p0.z, p0.w, p1.x, p1.y, p1.z, p1.w,
                 p2.x, p2.y, p2.z, p2.w, p3.x, p3.y, p3.z, p3.w};
    const float s = scale[g >> 1];

    // half2 for byte j: (high nibble, low nibble) * s
    uint32_t h2b[16];
#pragma unroll
    for (int j = 0; j < 16; j++)
        h2b[j] = h2u(c_codebook[(b[j] >> 4) & 15] * s, c_codebook[b[j] & 15] * s);

    // out uint4 #t = pairs from bytes {t, t+4, t+8, t+12}
    uint4* o = reinterpret_cast<uint4*>(g_W + (size_t)g * 32);
#pragma unroll
    for (int t = 0; t < 4; t++)
        o[t] = make_uint4(h2b[t], h2b[t + 4], h2b[t + 8], h2b[t + 12]);
}

// ---------------------------------------------------------------------------
// Permute + fp16-convert x: one thread -> one 32-float K-group.
// ---------------------------------------------------------------------------
__global__ void permute_x_kernel(const float* __restrict__ x) {
    const int g = blockIdx.x * blockDim.x + threadIdx.x;
    if (g >= (M_TOTAL * K_TOTAL) / 32) return;
    const float4* in = reinterpret_cast<const float4*>(x + (size_t)g * 32);
    float v[32];
#pragma unroll
    for (int q = 0; q < 8; q++) {
        float4 f = in[q];
        v[4 * q] = f.x; v[4 * q + 1] = f.y; v[4 * q + 2] = f.z; v[4 * q + 3] = f.w;
    }
    uint4* o = reinterpret_cast<uint4*>(g_X + (size_t)g * 32);
#pragma unroll
    for (int t = 0; t < 4; t++)
        o[t] = make_uint4(h2u(v[2 * t],      v[2 * t + 1]),
                          h2u(v[2 * t + 8],  v[2 * t + 9]),
                          h2u(v[2 * t + 16], v[2 * t + 17]),
                          h2u(v[2 * t + 24], v[2 * t + 25]));
}

// ---------------------------------------------------------------------------
// GEMM: C[M,N] = X[M,K] * W[N,K]^T + bias   (fp16 operands, fp32 accum)
// Block 128x128 x BK32, 256 threads = 8 warps (2m x 4n), warp tile 64x32.
// 5-stage cp.async pipeline, 16KB/stage.
// ---------------------------------------------------------------------------
#define BM 128
#define BN 128
#define BK 32                       // halves per k-tile (2 mma k-steps)
#define STAGES 5
#define ROW_BYTES 64                // BK * 2
#define A_STAGE_BYTES (BM * ROW_BYTES)    // 8192
#define STAGE_BYTES (2 * A_STAGE_BYTES)   // 16384
#define NUM_KTILES (K_TOTAL / BK)         // 128

__device__ __forceinline__ uint32_t smem_u32(const void* p) {
    uint32_t a;
    asm("{ .reg .u64 t; cvta.to.shared.u64 t, %1; cvt.u32.u64 %0, t; }" : "=r"(a) : "l"(p));
    return a;
}
__device__ __forceinline__ void cp16(uint32_t dst, const void* src) {
    asm volatile("cp.async.cg.shared.global [%0], [%1], 16;" :: "r"(dst), "l"(src));
}
__device__ __forceinline__ void cp_commit() { asm volatile("cp.async.commit_group;"); }
template <int N>
__device__ __forceinline__ void cp_wait() { asm volatile("cp.async.wait_group %0;" :: "n"(N)); }

__device__ __forceinline__ void mma_f16(float c[4], uint32_t a0, uint32_t a1,
                                        uint32_t a2, uint32_t a3,
                                        uint32_t b0, uint32_t b1) {
    asm volatile(
        "mma.sync.aligned.m16n8k16.row.col.f32.f16.f16.f32 "
        "{%0,%1,%2,%3}, {%4,%5,%6,%7}, {%8,%9}, {%0,%1,%2,%3};\n"
        : "+f"(c[0]), "+f"(c[1]), "+f"(c[2]), "+f"(c[3])
        : "r"(a0), "r"(a1), "r"(a2), "r"(a3), "r"(b0), "r"(b1));
}

__global__ void __launch_bounds__(256, 2)
gemm_f16_kernel(const float* __restrict__ bias, float* __restrict__ C)
{
    extern __shared__ __align__(16) char smem[];   // STAGES * STAGE_BYTES
    __shared__ float s_bias[BN];

    const int tid  = threadIdx.x;
    const int lane = tid & 31;
    const int wid  = tid >> 5;
    const int warp_m = wid & 1;
    const int warp_n = wid >> 1;
    const int gid = lane >> 2;
    const int tig = lane & 3;

    // Block swizzle: chunks of 8 m-tiles x 32 n-tiles (L2-friendly waves)
    const int bid   = blockIdx.x;
    const int chunk = bid >> 8;
    const int rres  = bid & 255;
    const int bm    = chunk * 8 + (rres & 7);   // 0..63
    const int bn    = rres >> 3;                // 0..31

    const __half* Ag = g_X + (size_t)bm * BM * K_TOTAL;
    const __half* Bg = g_W + (size_t)bn * BN * K_TOTAL;

    if (tid < BN) s_bias[tid] = bias[bn * BN + tid];

    // Copy addressing: 512 x 16B chunks per operand per tile; thread does
    // rows r0 and r0+64, chunk seg, for both A and B.
    const int r0  = tid >> 2;       // 0..63
    const int seg = tid & 3;        // 0..3
    const uint32_t smem_base = smem_u32(smem);
    const size_t g_off0 = (size_t)r0 * K_TOTAL + seg * 8;          // halves
    const size_t g_off1 = (size_t)(r0 + 64) * K_TOTAL + seg * 8;
    const uint32_t s_off = (uint32_t)(r0 * ROW_BYTES + seg * 16);  // bytes

    auto issue_tile = [&](int slot, int kt) {
        const uint32_t st = smem_base + (uint32_t)slot * STAGE_BYTES;
        const __half* a = Ag + (size_t)kt * BK;
        const __half* b = Bg + (size_t)kt * BK;
        cp16(st + s_off,                              a + g_off0);
        cp16(st + s_off + 64 * ROW_BYTES,             a + g_off1);
        cp16(st + s_off + A_STAGE_BYTES,              b + g_off0);
        cp16(st + s_off + A_STAGE_BYTES + 64 * ROW_BYTES, b + g_off1);
    };

    float acc[4][4][4];
#pragma unroll
    for (int mi = 0; mi < 4; mi++)
#pragma unroll
        for (int ni = 0; ni < 4; ni++)
#pragma unroll
            for (int i = 0; i < 4; i++) acc[mi][ni][i] = 0.0f;

#pragma unroll
    for (int s = 0; s < STAGES - 1; s++) { issue_tile(s, s); cp_commit(); }

    const int arow = warp_m * 64 + gid;
    const int brow = warp_n * 32 + gid;

    for (int kt = 0; kt < NUM_KTILES; kt++) {
        cp_wait<STAGES - 2>();
        __syncthreads();

        if (kt + STAGES - 1 < NUM_KTILES) issue_tile((kt + STAGES - 1) % STAGES, kt + STAGES - 1);
        cp_commit();

        const char* Asb = smem + (kt % STAGES) * STAGE_BYTES;
        const char* Bsb = Asb + A_STAGE_BYTES;

        // B fragments: one LDS.128 per ni covers both k-steps.
        uint4 bfr[4];
#pragma unroll
        for (int ni = 0; ni < 4; ni++)
            bfr[ni] = *reinterpret_cast<const uint4*>(
                Bsb + (brow + ni * 8) * ROW_BYTES + tig * 16);

#pragma unroll
        for (int mi = 0; mi < 4; mi++) {
            const uint4 alo = *reinterpret_cast<const uint4*>(
                Asb + (arow + mi * 16) * ROW_BYTES + tig * 16);
            const uint4 ahi = *reinterpret_cast<const uint4*>(
                Asb + (arow + mi * 16 + 8) * ROW_BYTES + tig * 16);
#pragma unroll
            for (int ni = 0; ni < 4; ni++) {
                // k-step 0 (k 0..15): pairs .x (k=2t,2t+1) and .y (k=2t+8,2t+9)
                mma_f16(acc[mi][ni], alo.x, ahi.x, alo.y, ahi.y, bfr[ni].x, bfr[ni].y);
                // k-step 1 (k 16..31): pairs .z and .w
                mma_f16(acc[mi][ni], alo.z, ahi.z, alo.w, ahi.w, bfr[ni].z, bfr[ni].w);
            }
        }
    }

    // Epilogue: C = acc + bias
    const int m_base = bm * BM + warp_m * 64;
    const int n_base = bn * BN + warp_n * 32;
#pragma unroll
    for (int mi = 0; mi < 4; mi++) {
#pragma unroll
        for (int ni = 0; ni < 4; ni++) {
            const int r = m_base + mi * 16 + gid;
            const int c = n_base + ni * 8 + tig * 2;
            const float b0 = s_bias[c - bn * BN];
            const float b1 = s_bias[c - bn * BN + 1];
            float2 v0 = make_float2(acc[mi][ni][0] + b0, acc[mi][ni][1] + b1);
            float2 v1 = make_float2(acc[mi][ni][2] + b0, acc[mi][ni][3] + b1);
            *reinterpret_cast<float2*>(C + (size_t)r * N_TOTAL + c)       = v0;
            *reinterpret_cast<float2*>(C + (size_t)(r + 8) * N_TOTAL + c) = v1;
        }
    }
}

// ---------------------------------------------------------------------------
// Launch
// ---------------------------------------------------------------------------
extern "C" void kernel_launch(void* const* d_in, const int* in_sizes, int n_in,
                              void* d_out, int out_size) {
    const float* x     = (const float*)d_in[0];   // [4,2048,4096]
    const int*   wp    = (const int*)d_in[1];     // packed bytes as int32
    const float* scale = (const float*)d_in[2];
    const float* bias  = (const float*)d_in[3];
    float*       out   = (float*)d_out;

    const int w_groups = (N_TOTAL * K_TOTAL) / 32;   // 524288
    const int x_groups = (M_TOTAL * K_TOTAL) / 32;   // 1048576
    dequant_permute_kernel<<<w_groups / 256, 256>>>(wp, scale);
    permute_x_kernel<<<x_groups / 256, 256>>>(x);

    static const int smem_bytes = STAGES * STAGE_BYTES;   // 80 KB
    cudaFuncSetAttribute(gemm_f16_kernel,
                         cudaFuncAttributeMaxDynamicSharedMemorySize, smem_bytes);
    const int grid = (M_TOTAL / BM) * (N_TOTAL / BN);   // 2048
    gemm_f16_kernel<<<grid, 256, smem_bytes>>>(bias, out);
}